// round 7
// baseline (speedup 1.0000x reference)
#include <cuda_runtime.h>
#include <cstdint>

// Problem constants (fixed shapes)
#define S_LEN   4096
#define D_DIM   64
#define H_NUM   16
#define B_NUM   2
#define W_WIN   256
#define C_BAND  513        // 2W+1

// Tiling
#define RT      64         // rows per CTA
#define CT      128        // k columns per chunk
#define NTHREADS 256
#define SCS     516        // score row stride (padded)

// smem layout (in floats)
#define QS_OFF  0                      // 64 rows * 64 = 4096
#define KS_OFF  4096                   // 2 bufs * 128*64 = 16384
#define SC_OFF  (4096 + 16384)         // 64 * 516 = 33024
#define SMEM_FLOATS (SC_OFF + RT * SCS)
#define SMEM_BYTES  (SMEM_FLOATS * 4)  // 214016 B

// ---- f32x2 packed FMA helpers (sm_100+) ----
__device__ __forceinline__ void ffma2u(unsigned long long& acc,
                                       unsigned long long a,
                                       unsigned long long b) {
    asm("fma.rn.f32x2 %0, %1, %2, %0;" : "+l"(acc) : "l"(a), "l"(b));
}
__device__ __forceinline__ float unpack_sum(unsigned long long v) {
    float lo, hi;
    asm("mov.b64 {%0, %1}, %2;" : "=f"(lo), "=f"(hi) : "l"(v));
    return lo + hi;
}

__device__ __forceinline__ void cp_async16(unsigned smem_addr, const void* gptr) {
    asm volatile("cp.async.cg.shared.global [%0], [%1], 16;" :: "r"(smem_addr), "l"(gptr));
}

// Copy one k chunk (CT rows x 64 floats) into swizzled smem buffer.
// Rows clamped to [0, S); scores from clamped rows are never stored (predicated).
__device__ __forceinline__ void load_k_chunk(const float* __restrict__ xb,
                                             int cb, float* kbuf, int tid) {
    #pragma unroll
    for (int p = 0; p < (CT * 16) / NTHREADS; p++) {
        int t   = tid + p * NTHREADS;
        int row = t >> 4;
        int f4  = t & 15;
        int jg  = cb + row;
        jg = jg < 0 ? 0 : (jg >= S_LEN ? S_LEN - 1 : jg);
        const float* src = xb + (size_t)jg * D_DIM + f4 * 4;
        unsigned dst = (unsigned)__cvta_generic_to_shared(
            kbuf + 4 * ((row << 4) + (f4 ^ (row & 7))));
        cp_async16(dst, src);
    }
}

__global__ void __launch_bounds__(NTHREADS, 1)
SlidingAttention_10230612099674_kernel(const float* __restrict__ x,
                                       float* __restrict__ out) {
    extern __shared__ float smem[];
    float* qs = smem + QS_OFF;
    float* ks = smem + KS_OFF;
    float* sc = smem + SC_OFF;

    const int tid = threadIdx.x;
    const int bh  = blockIdx.y;                    // b*16 + h
    const int i0  = blockIdx.x * RT;
    const float* xb = x + (size_t)bh * S_LEN * D_DIM;

    const float NEG_INF = __int_as_float(0xff800000);

    // Initialize score band to -inf (out-of-range positions stay -inf -> prob 0)
    for (int t = tid; t < RT * SCS; t += NTHREADS) sc[t] = NEG_INF;

    // Active chunk range: chunk ch covers columns [i0-256+128ch, +128)
    int ch_lo = 0, ch_hi = 4;
    while (i0 - 2 * W_WIN + CT * (ch_lo + 1) <= 0) ch_lo++;   // all cols < 0
    while (i0 - 2 * W_WIN + CT * ch_hi >= S_LEN) ch_hi--;     // all cols >= S
    const int nch = ch_hi - ch_lo + 1;

    // Group 0: q tile + first k chunk
    #pragma unroll
    for (int p = 0; p < (RT * 16) / NTHREADS; p++) {
        int t   = tid + p * NTHREADS;
        int row = t >> 4;
        int f4  = t & 15;
        const float* src = xb + (size_t)(i0 + row) * D_DIM + f4 * 4;
        unsigned dst = (unsigned)__cvta_generic_to_shared(
            qs + 4 * ((row << 4) + (f4 ^ (row & 7))));
        cp_async16(dst, src);
    }
    load_k_chunk(xb, i0 - 2 * W_WIN + CT * ch_lo, ks, tid);
    asm volatile("cp.async.commit_group;");

    const int ty = tid >> 5;   // warp id, 0..7 (row group)
    const int tx = tid & 31;   // lane, column group

    for (int m = 0; m < nch; m++) {
        __syncthreads();  // previous compute done before its buffer is overwritten
        if (m + 1 < nch) {
            load_k_chunk(xb, i0 - 2 * W_WIN + CT * (ch_lo + m + 1),
                         ks + ((m + 1) & 1) * (CT * D_DIM), tid);
            asm volatile("cp.async.commit_group;");
            asm volatile("cp.async.wait_group 1;");
        } else {
            asm volatile("cp.async.wait_group 0;");
        }
        __syncthreads();  // chunk m (and q) visible to all threads

        const float* kbuf = ks + (m & 1) * (CT * D_DIM);
        const int cb = i0 - 2 * W_WIN + CT * (ch_lo + m);

        unsigned long long acc[8][4];
        #pragma unroll
        for (int r = 0; r < 8; r++)
            #pragma unroll
            for (int c = 0; c < 4; c++) acc[r][c] = 0ull;

        #pragma unroll
        for (int d4 = 0; d4 < 16; d4++) {
            ulonglong2 kv[4];
            #pragma unroll
            for (int c = 0; c < 4; c++) {
                int j = tx + 32 * c;
                kv[c] = *reinterpret_cast<const ulonglong2*>(
                    kbuf + 4 * ((j << 4) + (d4 ^ (j & 7))));
            }
            #pragma unroll
            for (int r = 0; r < 8; r++) {
                int i = ty + 8 * r;
                ulonglong2 qv = *reinterpret_cast<const ulonglong2*>(
                    qs + 4 * ((i << 4) + (d4 ^ (i & 7))));
                #pragma unroll
                for (int c = 0; c < 4; c++) {
                    ffma2u(acc[r][c], qv.x, kv[c].x);
                    ffma2u(acc[r][c], qv.y, kv[c].y);
                }
            }
        }

        // Scatter this chunk's scores into the band (unique writer per (i,c))
        #pragma unroll
        for (int r = 0; r < 8; r++) {
            int il = ty + 8 * r;
            #pragma unroll
            for (int c = 0; c < 4; c++) {
                int jg = cb + tx + 32 * c;
                int cband = jg - (i0 + il) + W_WIN;
                if (jg >= 0 && jg < S_LEN && cband >= 0 && cband <= 2 * W_WIN)
                    sc[il * SCS + cband] = unpack_sum(acc[r][c]);
            }
        }
    }

    __syncthreads();

    // Softmax epilogue: warp ty handles rows ty*8 .. ty*8+7
    const int b = bh >> 4, h = bh & 15;
    for (int rr = 0; rr < 8; rr++) {
        int il = ty * 8 + rr;
        float v[17];
        float mx = NEG_INF;
        #pragma unroll
        for (int t = 0; t < 17; t++) {
            int c = tx + 32 * t;
            v[t] = (c < C_BAND) ? sc[il * SCS + c] : NEG_INF;
            mx = fmaxf(mx, v[t]);
        }
        #pragma unroll
        for (int o = 16; o > 0; o >>= 1)
            mx = fmaxf(mx, __shfl_xor_sync(0xffffffffu, mx, o));
        float z = 0.f;
        #pragma unroll
        for (int t = 0; t < 17; t++) { v[t] = __expf(v[t] - mx); z += v[t]; }
        #pragma unroll
        for (int o = 16; o > 0; o >>= 1)
            z += __shfl_xor_sync(0xffffffffu, z, o);
        float inv = 1.0f / z;

        float* orow = out + ((size_t)(b * S_LEN + (i0 + il)) * H_NUM + h) * C_BAND;
        #pragma unroll
        for (int t = 0; t < 17; t++) {
            int c = tx + 32 * t;
            if (c < C_BAND) orow[c] = v[t] * inv;
        }
    }
}

extern "C" void kernel_launch(void* const* d_in, const int* in_sizes, int n_in,
                              void* d_out, int out_size) {
    (void)in_sizes; (void)n_in; (void)out_size;
    const float* x = (const float*)d_in[0];
    float* out = (float*)d_out;

    cudaFuncSetAttribute(SlidingAttention_10230612099674_kernel,
                         cudaFuncAttributeMaxDynamicSharedMemorySize, SMEM_BYTES);

    dim3 grid(S_LEN / RT, B_NUM * H_NUM);   // (64, 32)
    SlidingAttention_10230612099674_kernel<<<grid, NTHREADS, SMEM_BYTES>>>(x, out);
}